// round 10
// baseline (speedup 1.0000x reference)
#include <cuda_runtime.h>
#include <cuda_fp16.h>
#include <cstdint>

// ---------------- problem constants ----------------
#define IN_C   64
#define IMG_H  256
#define IMG_W  256
#define OUT_C  128
#define OUT_H  254
#define OUT_W  254
#define NPOS   (IMG_H * IMG_W)          // 65536
#define NTAPS  9
#define OUT_HW (OUT_H * OUT_W)

// CTA tile: M=128 (all oc), N=128 (positions), K=64 per tap (R6 config)
#define N_TILE 128

// smem layout (R6)
#define SM_A        0                   // 2 stages x 16KB (w tap tile, 128x64 fp16)
#define A_STAGE     16384
#define SM_B        32768               // 3 strips (kh) x 136 rows x 128B
#define STRIP_STRIDE 17408              // 136*128, 1024-aligned
#define STRIP_CHUNKS 1040               // 130 rows x 8 chunks
#define SMEM_TOTAL  (32768 + 3 * STRIP_STRIDE)   // 84992

// ---------------- device scratch (no allocs allowed) ----------------
__device__ __align__(1024) __half g_x[NPOS * IN_C + 256];    // NHWC fp16 (+pad)
__device__ __align__(1024) __half g_w[NTAPS * OUT_C * IN_C]; // [tap][oc][ic] fp16

// ---------------- helpers ----------------
__device__ __forceinline__ uint32_t smem_u32(const void* p) {
    uint32_t a;
    asm("{ .reg .u64 t; cvta.to.shared.u64 t, %1; cvt.u32.u64 %0, t; }" : "=r"(a) : "l"(p));
    return a;
}
__device__ __forceinline__ uint32_t sw128(uint32_t o) { return o ^ ((o >> 3) & 0x70); }
__device__ __forceinline__ void cp_async16(uint32_t dst, const void* src) {
    asm volatile("cp.async.cg.shared.global [%0], [%1], 16;" :: "r"(dst), "l"(src) : "memory");
}
// L1-caching variant for weight tiles (re-read by successive CTA waves on the same SM)
__device__ __forceinline__ void cp_async16_ca(uint32_t dst, const void* src) {
    asm volatile("cp.async.ca.shared.global [%0], [%1], 16;" :: "r"(dst), "l"(src) : "memory");
}
__device__ __forceinline__ void cp_commit() {
    asm volatile("cp.async.commit_group;" ::: "memory");
}
template <int N>
__device__ __forceinline__ void cp_wait() {
    asm volatile("cp.async.wait_group %0;" :: "n"(N) : "memory");
}
__device__ __forceinline__ void ldsm4(uint32_t* r, uint32_t addr) {
    asm volatile("ldmatrix.sync.aligned.m8n8.x4.shared.b16 {%0,%1,%2,%3}, [%4];"
                 : "=r"(r[0]), "=r"(r[1]), "=r"(r[2]), "=r"(r[3]) : "r"(addr));
}
__device__ __forceinline__ void mma16816(float* d, const uint32_t* a, uint32_t b0, uint32_t b1) {
    asm volatile("mma.sync.aligned.m16n8k16.row.col.f32.f16.f16.f32 "
                 "{%0,%1,%2,%3}, {%4,%5,%6,%7}, {%8,%9}, {%0,%1,%2,%3};"
                 : "+f"(d[0]), "+f"(d[1]), "+f"(d[2]), "+f"(d[3])
                 : "r"(a[0]), "r"(a[1]), "r"(a[2]), "r"(a[3]), "r"(b0), "r"(b1));
}

// ---------------- fused prep kernel ----------------
// blocks [0,512): CHW fp32 -> NHWC fp16 transpose, 128 pos x 64 ic each.
// blocks [512,800): weight repack w[oc][ic][3][3] -> g_w[tap][oc][ic].
__global__ __launch_bounds__(256) void prep(const float* __restrict__ x,
                                            const float* __restrict__ w) {
    const int tid = threadIdx.x;
    if (blockIdx.x < 512) {
        __shared__ float s[IN_C][129];
        const int pos0 = blockIdx.x * 128;
        // read: 2048 float4 per block, 8 per thread, coalesced
#pragma unroll
        for (int i = 0; i < 8; i++) {
            const int r  = tid + i * 256;
            const int ic = r >> 5;                 // 32 float4-groups per ic
            const int p4 = (r & 31) * 4;
            float4 f = *reinterpret_cast<const float4*>(x + (size_t)ic * NPOS + pos0 + p4);
            s[ic][p4 + 0] = f.x; s[ic][p4 + 1] = f.y;
            s[ic][p4 + 2] = f.z; s[ic][p4 + 3] = f.w;
        }
        __syncthreads();
        // write: 1024 16B-chunks per block, 4 per thread, coalesced
#pragma unroll
        for (int i = 0; i < 4; i++) {
            const int c   = tid + i * 256;
            const int pos = c >> 3;
            const int ic0 = (c & 7) * 8;
            uint32_t pk[4];
#pragma unroll
            for (int j = 0; j < 4; j++) {
                __half h0 = __float2half(s[ic0 + 2*j][pos]);
                __half h1 = __float2half(s[ic0 + 2*j + 1][pos]);
                pk[j] = (uint32_t)__half_as_ushort(h0) | ((uint32_t)__half_as_ushort(h1) << 16);
            }
            *reinterpret_cast<uint4*>(g_x + (size_t)(pos0 + pos) * IN_C + ic0) =
                make_uint4(pk[0], pk[1], pk[2], pk[3]);
        }
    } else {
        const int idx = (blockIdx.x - 512) * 256 + tid;   // < 73728
        const int tap = idx >> 13;
        const int oc  = (idx >> 6) & 127;
        const int ic  = idx & 63;
        g_w[idx] = __float2half(w[((size_t)oc * IN_C + ic) * NTAPS + tap]);
    }
}

// ---------------- main HMMA conv kernel (R6 structure, verbatim) ----------------
// grid (2, 254): blockIdx.x = col tile (128 wide), blockIdx.y = output row
__global__ __launch_bounds__(256, 2)
void conv_hmma(const float* __restrict__ bias, float* __restrict__ out)
{
    extern __shared__ char smem[];
    const uint32_t sbase = smem_u32(smem);
    const int tid  = threadIdx.x;
    const int lane = tid & 31;
    const int wid  = tid >> 5;
    const int wm   = wid & 1;            // oc 0-63 / 64-127
    const int wn   = wid >> 1;           // 0..3, 32 positions each
    const int oh   = blockIdx.y;
    const int ow0  = blockIdx.x * N_TILE;

    // ldmatrix per-lane address components (validated mapping)
    const int rowA = ((lane >> 3) & 1) * 8 + (lane & 7);
    const int kbA  = (lane >> 4) * 16;
    const int rowB = ((lane >> 4) & 1) * 8 + (lane & 7);
    const int kbB  = ((lane >> 3) & 1) * 16;

    float acc[4][4][4];
#pragma unroll
    for (int a = 0; a < 4; a++)
#pragma unroll
        for (int b = 0; b < 4; b++)
#pragma unroll
            for (int c = 0; c < 4; c++) acc[a][b][c] = 0.0f;

    // ---- load the 3 B strips (once per CTA) ----
    auto issue_strips = [&]() {
        for (int i = tid; i < 3 * STRIP_CHUNKS; i += 256) {
            const int strip = i / STRIP_CHUNKS;
            const int c     = i - strip * STRIP_CHUNKS;
            const int y0    = (oh + strip) * IMG_W + ow0;
            cp_async16(sbase + SM_B + strip * STRIP_STRIDE + sw128((uint32_t)c * 16),
                       g_x + (size_t)y0 * IN_C + c * 8);
        }
    };
    // ---- load one weight tap tile into stage s (L1-cached: reused across waves) ----
    auto issue_A = [&](int tap, int s) {
        const __half* src = g_w + (size_t)tap * OUT_C * IN_C;
        const uint32_t sb = sbase + SM_A + s * A_STAGE;
#pragma unroll
        for (int i = 0; i < 4; i++) {
            const uint32_t chunk = tid + i * 256;          // 0..1023
            cp_async16_ca(sb + sw128(chunk * 16), src + chunk * 8);
        }
    };

    issue_strips();
    issue_A(0, 0);
    cp_commit();            // g0: strips + A0
    issue_A(1, 1);
    cp_commit();            // g1: A1

#pragma unroll 1
    for (int t = 0; t < NTAPS; t++) {
        if (t < NTAPS - 1) cp_wait<1>(); else cp_wait<0>();
        __syncthreads();

        const int kh = t / 3;
        const int kw = t - kh * 3;
        const uint32_t aBase = sbase + SM_A + (t & 1) * A_STAGE;
        const uint32_t bBase = sbase + SM_B + kh * STRIP_STRIDE;

#pragma unroll
        for (int kc = 0; kc < 4; kc++) {
            uint32_t a[4][4];
#pragma unroll
            for (int mi = 0; mi < 4; mi++) {
                const uint32_t o = (uint32_t)(wm * 64 + mi * 16 + rowA) * 128 + kc * 32 + kbA;
                ldsm4(a[mi], aBase + sw128(o));
            }
#pragma unroll
            for (int nj = 0; nj < 2; nj++) {
                uint32_t b[4];
                const uint32_t brow = (uint32_t)(kw + wn * 32 + nj * 16 + rowB);
                const uint32_t o = brow * 128 + kc * 32 + kbB;
                ldsm4(b, bBase + sw128(o));
#pragma unroll
                for (int mi = 0; mi < 4; mi++) {
                    mma16816(acc[mi][nj * 2],     a[mi], b[0], b[1]);
                    mma16816(acc[mi][nj * 2 + 1], a[mi], b[2], b[3]);
                }
            }
        }
        __syncthreads();
        if (t + 2 < NTAPS) { issue_A(t + 2, t & 1); cp_commit(); }
    }

    // ---- epilogue: direct gmem stores ----
#pragma unroll
    for (int mi = 0; mi < 4; mi++) {
        const int oc0 = wm * 64 + mi * 16 + (lane >> 2);
        const float b0 = bias[oc0];
        const float b1 = bias[oc0 + 8];
#pragma unroll
        for (int ni = 0; ni < 4; ni++) {
            const int owp = ow0 + wn * 32 + ni * 8 + (lane & 3) * 2;
            if (owp < OUT_W) {
                float2 v0 = make_float2(acc[mi][ni][0] + b0, acc[mi][ni][1] + b0);
                float2 v1 = make_float2(acc[mi][ni][2] + b1, acc[mi][ni][3] + b1);
                *reinterpret_cast<float2*>(out + (size_t)oc0 * OUT_HW + oh * OUT_W + owp) = v0;
                *reinterpret_cast<float2*>(out + (size_t)(oc0 + 8) * OUT_HW + oh * OUT_W + owp) = v1;
            }
        }
    }
}

// ---------------- launch ----------------
extern "C" void kernel_launch(void* const* d_in, const int* in_sizes, int n_in,
                              void* d_out, int out_size)
{
    const float* x    = (const float*)d_in[0];
    const float* w    = (const float*)d_in[1];
    const float* bias = (const float*)d_in[2];
    float* out        = (float*)d_out;

    cudaFuncSetAttribute(conv_hmma, cudaFuncAttributeMaxDynamicSharedMemorySize, SMEM_TOTAL);

    prep<<<512 + (NTAPS * OUT_C * IN_C) / 256, 256>>>(x, w);
    conv_hmma<<<dim3(2, OUT_H), 256, SMEM_TOTAL>>>(bias, out);
}

// round 11
// speedup vs baseline: 1.0300x; 1.0300x over previous
#include <cuda_runtime.h>
#include <cuda_fp16.h>
#include <cstdint>

// ---------------- problem constants ----------------
#define IN_C   64
#define IMG_H  256
#define IMG_W  256
#define OUT_C  128
#define OUT_H  254
#define OUT_W  254
#define NPOS   (IMG_H * IMG_W)          // 65536
#define NTAPS  9
#define OUT_HW (OUT_H * OUT_W)

// CTA tile: M=128 (all oc), N=128 (positions), K=64 per tap.
// 4 warps: 2 (M-halves) x 2 (N-halves), warp tile 64x64.
#define N_TILE 128

// smem layout (same footprint as R6)
#define SM_A        0                   // 2 stages x 16KB (w tap tile, 128x64 fp16, SW128)
#define A_STAGE     16384
#define SM_B        32768               // 3 strips (kh) x 136 rows x 128B (NHWC, SW128)
#define STRIP_STRIDE 17408              // 136*128
#define STRIP_CHUNKS 1040               // 130 rows x 8 chunks of 16B
#define SMEM_TOTAL  (32768 + 3 * STRIP_STRIDE)   // 84992

// ---------------- device scratch (no allocs allowed) ----------------
__device__ __align__(1024) __half g_x[NPOS * IN_C + 256];    // NHWC fp16 (+pad)
__device__ __align__(1024) __half g_w[NTAPS * OUT_C * IN_C]; // [tap][oc][ic] fp16

// ---------------- helpers ----------------
__device__ __forceinline__ uint32_t smem_u32(const void* p) {
    uint32_t a;
    asm("{ .reg .u64 t; cvta.to.shared.u64 t, %1; cvt.u32.u64 %0, t; }" : "=r"(a) : "l"(p));
    return a;
}
__device__ __forceinline__ uint32_t sw128(uint32_t o) { return o ^ ((o >> 3) & 0x70); }
__device__ __forceinline__ void cp_async16(uint32_t dst, const void* src) {
    asm volatile("cp.async.cg.shared.global [%0], [%1], 16;" :: "r"(dst), "l"(src) : "memory");
}
__device__ __forceinline__ void cp_commit() {
    asm volatile("cp.async.commit_group;" ::: "memory");
}
template <int N>
__device__ __forceinline__ void cp_wait() {
    asm volatile("cp.async.wait_group %0;" :: "n"(N) : "memory");
}
__device__ __forceinline__ void ldsm4(uint32_t* r, uint32_t addr) {
    asm volatile("ldmatrix.sync.aligned.m8n8.x4.shared.b16 {%0,%1,%2,%3}, [%4];"
                 : "=r"(r[0]), "=r"(r[1]), "=r"(r[2]), "=r"(r[3]) : "r"(addr));
}
__device__ __forceinline__ void mma16816(float* d, const uint32_t* a, uint32_t b0, uint32_t b1) {
    asm volatile("mma.sync.aligned.m16n8k16.row.col.f32.f16.f16.f32 "
                 "{%0,%1,%2,%3}, {%4,%5,%6,%7}, {%8,%9}, {%0,%1,%2,%3};"
                 : "+f"(d[0]), "+f"(d[1]), "+f"(d[2]), "+f"(d[3])
                 : "r"(a[0]), "r"(a[1]), "r"(a[2]), "r"(a[3]), "r"(b0), "r"(b1));
}

// ---------------- fused prep kernel (R10, unchanged) ----------------
// blocks [0,512): CHW fp32 -> NHWC fp16 transpose, 128 pos x 64 ic each.
// blocks [512,800): weight repack w[oc][ic][3][3] -> g_w[tap][oc][ic].
__global__ __launch_bounds__(256) void prep(const float* __restrict__ x,
                                            const float* __restrict__ w) {
    const int tid = threadIdx.x;
    if (blockIdx.x < 512) {
        __shared__ float s[IN_C][129];
        const int pos0 = blockIdx.x * 128;
#pragma unroll
        for (int i = 0; i < 8; i++) {
            const int r  = tid + i * 256;
            const int ic = r >> 5;
            const int p4 = (r & 31) * 4;
            float4 f = *reinterpret_cast<const float4*>(x + (size_t)ic * NPOS + pos0 + p4);
            s[ic][p4 + 0] = f.x; s[ic][p4 + 1] = f.y;
            s[ic][p4 + 2] = f.z; s[ic][p4 + 3] = f.w;
        }
        __syncthreads();
#pragma unroll
        for (int i = 0; i < 4; i++) {
            const int c   = tid + i * 256;
            const int pos = c >> 3;
            const int ic0 = (c & 7) * 8;
            uint32_t pk[4];
#pragma unroll
            for (int j = 0; j < 4; j++) {
                __half h0 = __float2half(s[ic0 + 2*j][pos]);
                __half h1 = __float2half(s[ic0 + 2*j + 1][pos]);
                pk[j] = (uint32_t)__half_as_ushort(h0) | ((uint32_t)__half_as_ushort(h1) << 16);
            }
            *reinterpret_cast<uint4*>(g_x + (size_t)(pos0 + pos) * IN_C + ic0) =
                make_uint4(pk[0], pk[1], pk[2], pk[3]);
        }
    } else {
        const int idx = (blockIdx.x - 512) * 256 + tid;   // < 73728
        const int tap = idx >> 13;
        const int oc  = (idx >> 6) & 127;
        const int ic  = idx & 63;
        g_w[idx] = __float2half(w[((size_t)oc * IN_C + ic) * NTAPS + tap]);
    }
}

// ---------------- main HMMA conv kernel: 4 warps, 64x64 warp tiles ----------------
// grid (2, 254): blockIdx.x = col tile (128 wide), blockIdx.y = output row
__global__ __launch_bounds__(128, 2)
void conv_hmma(const float* __restrict__ bias, float* __restrict__ out)
{
    extern __shared__ char smem[];
    const uint32_t sbase = smem_u32(smem);
    const int tid  = threadIdx.x;
    const int lane = tid & 31;
    const int wid  = tid >> 5;           // 0..3
    const int wm   = wid & 1;            // oc half: 0-63 / 64-127
    const int wn   = wid >> 1;           // pos half: 0-63 / 64-127
    const int oh   = blockIdx.y;
    const int ow0  = blockIdx.x * N_TILE;

    // ldmatrix per-lane address components (validated mapping)
    const int rowA = ((lane >> 3) & 1) * 8 + (lane & 7);
    const int kbA  = (lane >> 4) * 16;
    const int rowB = ((lane >> 4) & 1) * 8 + (lane & 7);
    const int kbB  = ((lane >> 3) & 1) * 16;

    // acc[mi][n8][4]: mi = 16-row M block, n8 = 8-pos N block (8 of them = 64 pos)
    float acc[4][8][4];
#pragma unroll
    for (int a = 0; a < 4; a++)
#pragma unroll
        for (int b = 0; b < 8; b++)
#pragma unroll
            for (int c = 0; c < 4; c++) acc[a][b][c] = 0.0f;

    // ---- load the 3 B strips (once per CTA) ----
    auto issue_strips = [&]() {
        for (int i = tid; i < 3 * STRIP_CHUNKS; i += 128) {
            const int strip = i / STRIP_CHUNKS;
            const int c     = i - strip * STRIP_CHUNKS;
            const int y0    = (oh + strip) * IMG_W + ow0;
            cp_async16(sbase + SM_B + strip * STRIP_STRIDE + sw128((uint32_t)c * 16),
                       g_x + (size_t)y0 * IN_C + c * 8);
        }
    };
    // ---- load one weight tap tile (128x64 fp16 = 1024 chunks) into stage s ----
    auto issue_A = [&](int tap, int s) {
        const __half* src = g_w + (size_t)tap * OUT_C * IN_C;
        const uint32_t sb = sbase + SM_A + s * A_STAGE;
#pragma unroll
        for (int i = 0; i < 8; i++) {
            const uint32_t chunk = tid + i * 128;          // 0..1023
            cp_async16(sb + sw128(chunk * 16), src + chunk * 8);
        }
    };

    issue_strips();
    issue_A(0, 0);
    cp_commit();            // g0: strips + A0
    issue_A(1, 1);
    cp_commit();            // g1: A1

#pragma unroll 1
    for (int t = 0; t < NTAPS; t++) {
        if (t < NTAPS - 1) cp_wait<1>(); else cp_wait<0>();
        __syncthreads();

        const int kh = t / 3;
        const int kw = t - kh * 3;
        const uint32_t aBase = sbase + SM_A + (t & 1) * A_STAGE;
        const uint32_t bBase = sbase + SM_B + kh * STRIP_STRIDE;

#pragma unroll
        for (int kc = 0; kc < 4; kc++) {
            uint32_t a[4][4];
#pragma unroll
            for (int mi = 0; mi < 4; mi++) {
                const uint32_t o = (uint32_t)(wm * 64 + mi * 16 + rowA) * 128 + kc * 32 + kbA;
                ldsm4(a[mi], aBase + sw128(o));
            }
#pragma unroll
            for (int nj = 0; nj < 4; nj++) {               // 4 x 16-pos groups = 64 pos
                uint32_t b[4];
                const uint32_t brow = (uint32_t)(kw + wn * 64 + nj * 16 + rowB);
                const uint32_t o = brow * 128 + kc * 32 + kbB;
                ldsm4(b, bBase + sw128(o));
#pragma unroll
                for (int mi = 0; mi < 4; mi++) {
                    mma16816(acc[mi][nj * 2],     a[mi], b[0], b[1]);
                    mma16816(acc[mi][nj * 2 + 1], a[mi], b[2], b[3]);
                }
            }
        }
        __syncthreads();
        if (t + 2 < NTAPS) { issue_A(t + 2, t & 1); cp_commit(); }
    }

    // ---- epilogue: direct gmem stores ----
#pragma unroll
    for (int mi = 0; mi < 4; mi++) {
        const int oc0 = wm * 64 + mi * 16 + (lane >> 2);
        const float b0 = bias[oc0];
        const float b1 = bias[oc0 + 8];
#pragma unroll
        for (int n8 = 0; n8 < 8; n8++) {
            const int owp = ow0 + wn * 64 + n8 * 8 + (lane & 3) * 2;
            if (owp < OUT_W) {
                float2 v0 = make_float2(acc[mi][n8][0] + b0, acc[mi][n8][1] + b0);
                float2 v1 = make_float2(acc[mi][n8][2] + b1, acc[mi][n8][3] + b1);
                *reinterpret_cast<float2*>(out + (size_t)oc0 * OUT_HW + oh * OUT_W + owp) = v0;
                *reinterpret_cast<float2*>(out + (size_t)(oc0 + 8) * OUT_HW + oh * OUT_W + owp) = v1;
            }
        }
    }
}

// ---------------- launch ----------------
extern "C" void kernel_launch(void* const* d_in, const int* in_sizes, int n_in,
                              void* d_out, int out_size)
{
    const float* x    = (const float*)d_in[0];
    const float* w    = (const float*)d_in[1];
    const float* bias = (const float*)d_in[2];
    float* out        = (float*)d_out;

    cudaFuncSetAttribute(conv_hmma, cudaFuncAttributeMaxDynamicSharedMemorySize, SMEM_TOTAL);

    prep<<<512 + (NTAPS * OUT_C * IN_C) / 256, 256>>>(x, w);
    conv_hmma<<<dim3(2, OUT_H), 128, SMEM_TOTAL>>>(bias, out);
}

// round 12
// speedup vs baseline: 1.0507x; 1.0201x over previous
#include <cuda_runtime.h>
#include <cuda_fp16.h>
#include <cstdint>

// ---------------- problem constants ----------------
#define IN_C   64
#define IMG_H  256
#define IMG_W  256
#define OUT_C  128
#define OUT_H  254
#define OUT_W  254
#define NPOS   (IMG_H * IMG_W)          // 65536
#define NTAPS  9
#define OUT_HW (OUT_H * OUT_W)

// CTA tile: M=128 (all oc), N=128 (positions), K=64 per tap (R6 layout)
#define N_TILE 128

// smem: 2 stages x (2 taps x 16KB) A  +  3 B strips (130 rows x 128B)
#define SM_A          0
#define A_TAP         16384              // one tap tile
#define A_STAGE       32768              // two taps per stage
#define SM_B          65536
#define STRIP_STRIDE  16640              // 130*128
#define STRIP_CHUNKS  1040               // 130 rows x 8 chunks of 16B
#define SMEM_TOTAL    (65536 + 3 * STRIP_STRIDE)   // 115456  (<=116736 for 2 CTA/SM)

// ---------------- device scratch (no allocs allowed) ----------------
__device__ __align__(1024) __half g_x[NPOS * IN_C + 256];    // NHWC fp16 (+pad)
__device__ __align__(1024) __half g_w[NTAPS * OUT_C * IN_C]; // [tap][oc][ic] fp16

// ---------------- helpers ----------------
__device__ __forceinline__ uint32_t smem_u32(const void* p) {
    uint32_t a;
    asm("{ .reg .u64 t; cvta.to.shared.u64 t, %1; cvt.u32.u64 %0, t; }" : "=r"(a) : "l"(p));
    return a;
}
__device__ __forceinline__ uint32_t sw128(uint32_t o) { return o ^ ((o >> 3) & 0x70); }
__device__ __forceinline__ void cp_async16(uint32_t dst, const void* src) {
    asm volatile("cp.async.cg.shared.global [%0], [%1], 16;" :: "r"(dst), "l"(src) : "memory");
}
__device__ __forceinline__ void cp_commit() {
    asm volatile("cp.async.commit_group;" ::: "memory");
}
template <int N>
__device__ __forceinline__ void cp_wait() {
    asm volatile("cp.async.wait_group %0;" :: "n"(N) : "memory");
}
__device__ __forceinline__ void ldsm4(uint32_t* r, uint32_t addr) {
    asm volatile("ldmatrix.sync.aligned.m8n8.x4.shared.b16 {%0,%1,%2,%3}, [%4];"
                 : "=r"(r[0]), "=r"(r[1]), "=r"(r[2]), "=r"(r[3]) : "r"(addr));
}
__device__ __forceinline__ void mma16816(float* d, const uint32_t* a, uint32_t b0, uint32_t b1) {
    asm volatile("mma.sync.aligned.m16n8k16.row.col.f32.f16.f16.f32 "
                 "{%0,%1,%2,%3}, {%4,%5,%6,%7}, {%8,%9}, {%0,%1,%2,%3};"
                 : "+f"(d[0]), "+f"(d[1]), "+f"(d[2]), "+f"(d[3])
                 : "r"(a[0]), "r"(a[1]), "r"(a[2]), "r"(a[3]), "r"(b0), "r"(b1));
}

// ---------------- fused prep kernel (unchanged) ----------------
__global__ __launch_bounds__(256) void prep(const float* __restrict__ x,
                                            const float* __restrict__ w) {
    const int tid = threadIdx.x;
    if (blockIdx.x < 512) {
        __shared__ float s[IN_C][129];
        const int pos0 = blockIdx.x * 128;
#pragma unroll
        for (int i = 0; i < 8; i++) {
            const int r  = tid + i * 256;
            const int ic = r >> 5;
            const int p4 = (r & 31) * 4;
            float4 f = *reinterpret_cast<const float4*>(x + (size_t)ic * NPOS + pos0 + p4);
            s[ic][p4 + 0] = f.x; s[ic][p4 + 1] = f.y;
            s[ic][p4 + 2] = f.z; s[ic][p4 + 3] = f.w;
        }
        __syncthreads();
#pragma unroll
        for (int i = 0; i < 4; i++) {
            const int c   = tid + i * 256;
            const int pos = c >> 3;
            const int ic0 = (c & 7) * 8;
            uint32_t pk[4];
#pragma unroll
            for (int j = 0; j < 4; j++) {
                __half h0 = __float2half(s[ic0 + 2*j][pos]);
                __half h1 = __float2half(s[ic0 + 2*j + 1][pos]);
                pk[j] = (uint32_t)__half_as_ushort(h0) | ((uint32_t)__half_as_ushort(h1) << 16);
            }
            *reinterpret_cast<uint4*>(g_x + (size_t)(pos0 + pos) * IN_C + ic0) =
                make_uint4(pk[0], pk[1], pk[2], pk[3]);
        }
    } else {
        const int idx = (blockIdx.x - 512) * 256 + tid;   // < 73728
        const int tap = idx >> 13;
        const int oc  = (idx >> 6) & 127;
        const int ic  = idx & 63;
        g_w[idx] = __float2half(w[((size_t)oc * IN_C + ic) * NTAPS + tap]);
    }
}

// ---------------- main HMMA conv kernel: R6 layout, 2-tap pipeline stages ----------
// grid (2, 254): blockIdx.x = col tile (128 wide), blockIdx.y = output row
__global__ __launch_bounds__(256, 2)
void conv_hmma(const float* __restrict__ bias, float* __restrict__ out)
{
    extern __shared__ char smem[];
    const uint32_t sbase = smem_u32(smem);
    const int tid  = threadIdx.x;
    const int lane = tid & 31;
    const int wid  = tid >> 5;
    const int wm   = wid & 1;            // oc 0-63 / 64-127
    const int wn   = wid >> 1;           // 0..3, 32 positions each
    const int oh   = blockIdx.y;
    const int ow0  = blockIdx.x * N_TILE;

    // ldmatrix per-lane address components (validated mapping)
    const int rowA = ((lane >> 3) & 1) * 8 + (lane & 7);
    const int kbA  = (lane >> 4) * 16;
    const int rowB = ((lane >> 4) & 1) * 8 + (lane & 7);
    const int kbB  = ((lane >> 3) & 1) * 16;

    float acc[4][4][4];
#pragma unroll
    for (int a = 0; a < 4; a++)
#pragma unroll
        for (int b = 0; b < 4; b++)
#pragma unroll
            for (int c = 0; c < 4; c++) acc[a][b][c] = 0.0f;

    // ---- load the 3 B strips (once per CTA) ----
    auto issue_strips = [&]() {
        for (int i = tid; i < 3 * STRIP_CHUNKS; i += 256) {
            const int strip = i / STRIP_CHUNKS;
            const int c     = i - strip * STRIP_CHUNKS;
            const int y0    = (oh + strip) * IMG_W + ow0;
            cp_async16(sbase + SM_B + strip * STRIP_STRIDE + sw128((uint32_t)c * 16),
                       g_x + (size_t)y0 * IN_C + c * 8);
        }
    };
    // ---- load a PAIR of weight taps (2p, 2p+1) into stage s ----
    auto issue_A_pair = [&](int p, int s) {
        const uint32_t sb = sbase + SM_A + s * A_STAGE;
#pragma unroll
        for (int h = 0; h < 2; h++) {
            const int tap = 2 * p + h;
            if (tap < NTAPS) {
                const __half* src = g_w + (size_t)tap * OUT_C * IN_C;
#pragma unroll
                for (int i = 0; i < 4; i++) {
                    const uint32_t chunk = tid + i * 256;   // 0..1023
                    cp_async16(sb + h * A_TAP + sw128(chunk * 16), src + chunk * 8);
                }
            }
        }
    };

    issue_strips();
    issue_A_pair(0, 0);
    cp_commit();            // g0: strips + taps 0,1
    issue_A_pair(1, 1);
    cp_commit();            // g1: taps 2,3

#pragma unroll 1
    for (int p = 0; p < 5; p++) {        // tap pairs (0,1)(2,3)(4,5)(6,7)(8)
        if (p < 4) cp_wait<1>(); else cp_wait<0>();
        __syncthreads();

        const int tlim = (2 * p + 1 < NTAPS) ? 2 : 1;
#pragma unroll
        for (int h = 0; h < 2; h++) {
            if (h >= tlim) break;
            const int t  = 2 * p + h;
            const int kh = t / 3;
            const int kw = t - kh * 3;
            const uint32_t aBase = sbase + SM_A + (p & 1) * A_STAGE + h * A_TAP;
            const uint32_t bBase = sbase + SM_B + kh * STRIP_STRIDE;

#pragma unroll
            for (int kc = 0; kc < 4; kc++) {
                uint32_t a[4][4];
#pragma unroll
                for (int mi = 0; mi < 4; mi++) {
                    const uint32_t o = (uint32_t)(wm * 64 + mi * 16 + rowA) * 128 + kc * 32 + kbA;
                    ldsm4(a[mi], aBase + sw128(o));
                }
#pragma unroll
                for (int nj = 0; nj < 2; nj++) {
                    uint32_t b[4];
                    const uint32_t brow = (uint32_t)(kw + wn * 32 + nj * 16 + rowB);
                    const uint32_t o = brow * 128 + kc * 32 + kbB;
                    ldsm4(b, bBase + sw128(o));
#pragma unroll
                    for (int mi = 0; mi < 4; mi++) {
                        mma16816(acc[mi][nj * 2],     a[mi], b[0], b[1]);
                        mma16816(acc[mi][nj * 2 + 1], a[mi], b[2], b[3]);
                    }
                }
            }
        }
        __syncthreads();
        if (p + 2 < 5) { issue_A_pair(p + 2, p & 1); cp_commit(); }
    }

    // ---- epilogue: direct gmem stores ----
#pragma unroll
    for (int mi = 0; mi < 4; mi++) {
        const int oc0 = wm * 64 + mi * 16 + (lane >> 2);
        const float b0 = bias[oc0];
        const float b1 = bias[oc0 + 8];
#pragma unroll
        for (int ni = 0; ni < 4; ni++) {
            const int owp = ow0 + wn * 32 + ni * 8 + (lane & 3) * 2;
            if (owp < OUT_W) {
                float2 v0 = make_float2(acc[mi][ni][0] + b0, acc[mi][ni][1] + b0);
                float2 v1 = make_float2(acc[mi][ni][2] + b1, acc[mi][ni][3] + b1);
                *reinterpret_cast<float2*>(out + (size_t)oc0 * OUT_HW + oh * OUT_W + owp) = v0;
                *reinterpret_cast<float2*>(out + (size_t)(oc0 + 8) * OUT_HW + oh * OUT_W + owp) = v1;
            }
        }
    }
}

// ---------------- launch ----------------
extern "C" void kernel_launch(void* const* d_in, const int* in_sizes, int n_in,
                              void* d_out, int out_size)
{
    const float* x    = (const float*)d_in[0];
    const float* w    = (const float*)d_in[1];
    const float* bias = (const float*)d_in[2];
    float* out        = (float*)d_out;

    cudaFuncSetAttribute(conv_hmma, cudaFuncAttributeMaxDynamicSharedMemorySize, SMEM_TOTAL);

    prep<<<512 + (NTAPS * OUT_C * IN_C) / 256, 256>>>(x, w);
    conv_hmma<<<dim3(2, OUT_H), 256, SMEM_TOTAL>>>(bias, out);
}